// round 15
// baseline (speedup 1.0000x reference)
#include <cuda_runtime.h>
#include <cuda_fp16.h>
#include <math.h>
#include <stdint.h>

#define NN 32
#define LL 8192
#define CO 128
#define CI1 64
#define TT 10
#define LO 4096

// ---------------- scratch (__device__ globals; no allocation) ----------------
__device__ __align__(128) __half g_hh[(size_t)NN * LL * CO];
__device__ __align__(128) __half g_ssh[(size_t)NN * LL * CO];
__device__ __align__(128) __half g_y[(size_t)NN * CO * LL];
__device__ __align__(128) float g_xd[(size_t)NN * CO * LO];
__device__ __align__(128) __half g_w1h[(size_t)NN * 5 * 1 * CO * 64];
__device__ __align__(128) __half g_w2h[(size_t)NN * 5 * 2 * CO * 64];
__device__ __align__(128) __half g_wdh[4 * CO * 64];
__device__ float g_s1[NN * CO];
__device__ float g_s2[NN * CO];
__device__ float g_b1[CO];
__device__ float g_b2[CO];

// ---------------- small device helpers ----------------
// Fast mish: x * tanh(softplus(x)) = x*((1+e)^2-1)/((1+e)^2+1), e = exp(x).
__device__ __forceinline__ float mishf(float v) {
    if (v > 8.f) return v;
    float e = __expf(v);
    float t = 1.f + e;
    float t2 = t * t;
    return v * __fdividef(t2 - 1.f, t2 + 1.f);
}
__device__ __forceinline__ uint32_t smem_u32(const void* p) {
    uint32_t a;
    asm("{ .reg .u64 t; cvta.to.shared.u64 t, %1; cvt.u32.u64 %0, t; }" : "=r"(a) : "l"(p));
    return a;
}
__device__ __forceinline__ void cp16(uint32_t dst, const void* src) {
    asm volatile("cp.async.cg.shared.global [%0], [%1], 16;" :: "r"(dst), "l"(src));
}
__device__ __forceinline__ void cp_commit() {
    asm volatile("cp.async.commit_group;" ::: "memory");
}
template <int N>
__device__ __forceinline__ void cp_wait() {
    asm volatile("cp.async.wait_group %0;" :: "n"(N) : "memory");
}
__device__ __forceinline__ void ldsm4(uint32_t* r, uint32_t addr) {
    asm volatile("ldmatrix.sync.aligned.m8n8.x4.shared.b16 {%0,%1,%2,%3}, [%4];"
                 : "=r"(r[0]), "=r"(r[1]), "=r"(r[2]), "=r"(r[3]) : "r"(addr));
}
__device__ __forceinline__ void mma_f16(float* d, const uint32_t* a, const uint32_t* b) {
    asm volatile("mma.sync.aligned.m16n8k16.row.col.f32.f16.f16.f32 "
                 "{%0,%1,%2,%3}, {%4,%5,%6,%7}, {%8,%9}, {%0,%1,%2,%3};"
                 : "+f"(d[0]), "+f"(d[1]), "+f"(d[2]), "+f"(d[3])
                 : "r"(a[0]), "r"(a[1]), "r"(a[2]), "r"(a[3]), "r"(b[0]), "r"(b[1]));
}

// ============================================================================
// Conv-as-GEMM, warp-level fp16 MMA (single fp16 W).
// XT = __half (cp.async fill, committed as its own group) or float (fp32
// source converted in the loader with plain stores).
// YT = __half (layers 1/2) or float (downsample). Fused stats.
// CTA = 256 threads (8 warps, 2x4); tile M=64 (o-half, blockIdx.z) x NT.
// ============================================================================
template <int CI, int NSHIFT, int RS, int HALO, int NT, bool PER_N_STATS,
          typename YT, typename XT>
__global__ void __launch_bounds__(256, 2)
mma_conv(const XT* __restrict__ X,
         const __half* __restrict__ Wh,
         YT* __restrict__ Y, float* __restrict__ S1, float* __restrict__ S2,
         size_t x_nstride, size_t w_nstride, int outL)
{
    constexpr int HF = CI / 64;
    constexpr int P = NSHIFT * HF;
    constexpr int XR = NT * RS + HALO;
    constexpr int XPITCH = CI * 2 + 16;      // bytes; row step ≡ 4 banks (mod 32)
    constexpr int WPITCH = 144;
    constexpr int WCH = 64 * WPITCH;
    constexpr int XT_B = XR * XPITCH;
    constexpr int SEGR = CI / 8;
    constexpr int NB = NT / 64;
    constexpr int NFR = 2 * NB;

    extern __shared__ char sm[];
    const uint32_t base = smem_u32(sm);
    const uint32_t x_s = base;
    const uint32_t w_s = base + XT_B;

    const int tid = threadIdx.x;
    const int n = blockIdx.y;
    const int l0 = blockIdx.x * NT;
    const int o_base = blockIdx.z * 64;

    // W piece 0 (committed group; overlaps the X fill below)
    auto load_w = [&](int piece, int buf) {
        const __half* ph = Wh + (size_t)n * w_nstride + (size_t)piece * (CO * 64)
                           + (size_t)o_base * 64;
        uint32_t dst = w_s + (uint32_t)buf * WCH;
        for (int s = tid; s < 512; s += 256) {
            int r = s >> 3, c = s & 7;
            cp16(dst + r * WPITCH + c * 16, ph + r * 64 + c * 8);
        }
        cp_commit();
    };
    load_w(0, 0);

    // ---------------- X tile fill ----------------
    if (sizeof(XT) == 4) {
        // fp32 source: load float4, convert to fp16, plain smem stores
        const float* gx = (const float*)X + (size_t)n * x_nstride;
        constexpr int SEGF = CI / 4;
        for (int s = tid; s < XR * SEGF; s += 256) {
            int r = s / SEGF, c = s % SEGF;
            long l = (long)l0 * RS - HALO + r;
            float4 v = make_float4(0.f, 0.f, 0.f, 0.f);
            if (l >= 0) v = *(const float4*)(gx + (size_t)l * CI + (size_t)c * 4);
            *(__half2*)(sm + r * XPITCH + c * 8)     = __floats2half2_rn(v.x, v.y);
            *(__half2*)(sm + r * XPITCH + c * 8 + 4) = __floats2half2_rn(v.z, v.w);
        }
    } else {
        if (HALO > 0 && blockIdx.x == 0) {
            const uint4 z = make_uint4(0, 0, 0, 0);
            for (int s = tid; s < HALO * SEGR; s += 256) {
                int r = s / SEGR, c = s % SEGR;
                *(uint4*)(sm + r * XPITCH + c * 16) = z;
            }
        }
        const __half* gx = (const __half*)X + (size_t)n * x_nstride;
        for (int s = tid; s < XR * SEGR; s += 256) {
            int r = s / SEGR, c = s % SEGR;
            long l = (long)l0 * RS - HALO + r;
            if (l >= 0)
                cp16(x_s + r * XPITCH + c * 16, gx + (size_t)l * CI + (size_t)c * 8);
        }
        cp_commit();   // X tile gets its OWN committed group (load_w committed before us)
    }

    const int warp = tid >> 5, lane = tid & 31;
    const int o0w = (warp >> 2) * 32;
    const int n0w = (warp & 3) * (NT / 4);
    const int a_row = (lane & 7) + ((lane >> 3) & 1) * 8;
    const int a_csh = (lane >> 4) * 8;
    const int b_jj = (lane & 7) + ((lane >> 4) << 3);
    const int b_csh = ((lane >> 3) & 1) * 8;

    float acc[2][NFR][4];
#pragma unroll
    for (int mi = 0; mi < 2; mi++)
#pragma unroll
        for (int nf = 0; nf < NFR; nf++)
#pragma unroll
            for (int q = 0; q < 4; q++) acc[mi][nf][q] = 0.f;

    for (int p = 0; p < P; p++) {
        cp_wait<0>();
        __syncthreads();   // readers of buffer (p+1)&1 (= piece p-1) are done
        if (p + 1 < P) load_w(p + 1, (p + 1) & 1);

        const int k = p / HF, hf = p % HF;
        const uint32_t wh_b = w_s + (uint32_t)(p & 1) * WCH;

#pragma unroll
        for (int i16 = 0; i16 < 4; i16++) {
            const int i0 = i16 * 16;
            uint32_t Ah[2][4];
#pragma unroll
            for (int mi = 0; mi < 2; mi++) {
                uint32_t ao = (uint32_t)((o0w + a_row + mi * 16) * WPITCH + (i0 + a_csh) * 2);
                ldsm4(Ah[mi], wh_b + ao);
            }
            const int xcol = (hf * 64 + i0 + b_csh) * 2;
#pragma unroll
            for (int nb = 0; nb < NB; nb++) {
                uint32_t B[4];
                uint32_t xo = (uint32_t)((RS * (n0w + nb * 16 + b_jj) + k) * XPITCH + xcol);
                ldsm4(B, x_s + xo);
#pragma unroll
                for (int mi = 0; mi < 2; mi++)
#pragma unroll
                    for (int hl = 0; hl < 2; hl++)
                        mma_f16(acc[mi][nb * 2 + hl], Ah[mi], &B[hl * 2]);
            }
        }
    }

    // ---------------- epilogue: store + fused stats ----------------
    const int g = lane >> 2, tg = lane & 3;
#pragma unroll
    for (int mi = 0; mi < 2; mi++) {
        const int o = o_base + o0w + mi * 16 + g;
        YT* row0 = Y + ((size_t)(n * CO + o)) * outL + l0 + n0w;
        YT* row1 = row0 + (size_t)8 * outL;
#pragma unroll
        for (int nf = 0; nf < NFR; nf++) {
            int c = nf * 8 + tg * 2;
            if (sizeof(YT) == 2) {
                *(__half2*)((__half*)row0 + c) = __floats2half2_rn(acc[mi][nf][0], acc[mi][nf][1]);
                *(__half2*)((__half*)row1 + c) = __floats2half2_rn(acc[mi][nf][2], acc[mi][nf][3]);
            } else {
                *(float2*)((float*)row0 + c) = make_float2(acc[mi][nf][0], acc[mi][nf][1]);
                *(float2*)((float*)row1 + c) = make_float2(acc[mi][nf][2], acc[mi][nf][3]);
            }
        }
    }
    float ts[4], tq[4];
#pragma unroll
    for (int r = 0; r < 4; r++) { ts[r] = 0.f; tq[r] = 0.f; }
#pragma unroll
    for (int mi = 0; mi < 2; mi++)
#pragma unroll
        for (int nf = 0; nf < NFR; nf++) {
            float a0 = acc[mi][nf][0], a1 = acc[mi][nf][1];
            float a2 = acc[mi][nf][2], a3 = acc[mi][nf][3];
            ts[2 * mi]     += a0 + a1;  tq[2 * mi]     += a0 * a0 + a1 * a1;
            ts[2 * mi + 1] += a2 + a3;  tq[2 * mi + 1] += a2 * a2 + a3 * a3;
        }
#pragma unroll
    for (int r = 0; r < 4; r++) {
        ts[r] += __shfl_xor_sync(0xffffffffu, ts[r], 1);
        ts[r] += __shfl_xor_sync(0xffffffffu, ts[r], 2);
        tq[r] += __shfl_xor_sync(0xffffffffu, tq[r], 1);
        tq[r] += __shfl_xor_sync(0xffffffffu, tq[r], 2);
    }
    if (tg == 0) {
        const int sbase = PER_N_STATS ? n * CO : 0;
#pragma unroll
        for (int r = 0; r < 4; r++) {
            int o = o_base + o0w + (r >> 1) * 16 + g + (r & 1) * 8;
            atomicAdd(&S1[sbase + o], ts[r]);
            atomicAdd(&S2[sbase + o], tq[r]);
        }
    }
}

// ---------------- gate + per-sample weights (fp16) ----------------
__global__ void __launch_bounds__(512)
gate_weights_kernel(const float* __restrict__ t,
                    const float* __restrict__ gw,
                    const float* __restrict__ gb,
                    const float* __restrict__ k5,
                    const float* __restrict__ k3,
                    const float* __restrict__ k1,
                    const float* __restrict__ a3,
                    const float* __restrict__ a5,
                    __half* __restrict__ wh,
                    float* __restrict__ S1, float* __restrict__ S2,
                    int CI)
{
    const int n = blockIdx.x;
    const int hf = blockIdx.y;
    const int HF = gridDim.y;
    const int oc = blockIdx.z;
    const int tid = threadIdx.x;

    __shared__ float gs[5][128];
    if (tid < 128) {
        const int o = tid;
        if (blockIdx.y == 0 && blockIdx.z == 0) {
            S1[n * CO + o] = 0.f;
            S2[n * CO + o] = 0.f;
        }
        float tv[TT];
#pragma unroll
        for (int j = 0; j < TT; j++) tv[j] = t[n * TT + j];
        float g[5];
        float mx = -1e30f;
#pragma unroll
        for (int e = 0; e < 5; e++) {
            float s = gb[e * CO + o];
            const float* gwr = gw + (size_t)(e * CO + o) * TT;
#pragma unroll
            for (int j = 0; j < TT; j++) s += tv[j] * gwr[j];
            g[e] = s;
            mx = fmaxf(mx, s);
        }
        float den = 0.f;
#pragma unroll
        for (int e = 0; e < 5; e++) { g[e] = expf(g[e] - mx); den += g[e]; }
        float inv = 1.f / den;
        gs[0][o] = g[0] * inv;
        gs[1][o] = g[1] * inv;
        gs[2][o] = g[2] * inv;
        gs[3][o] = g[3] * inv * (1.f / 3.f);
        gs[4][o] = g[4] * inv * 0.2f;
    }
    __syncthreads();

    const int og = tid >> 6;
    const int ii = tid & 63;
    const int i = hf * 64 + ii;
    const size_t kstride = (size_t)HF * 128 * 64;

#pragma unroll
    for (int oj = 0; oj < 4; oj++) {
        const int o = oc * 32 + oj * 8 + og;
        const float g0 = gs[0][o], g1 = gs[1][o], g2 = gs[2][o];
        const float g3v = gs[3][o], g4v = gs[4][o];
        const int oi = o * CI + i;
        const float* p5 = k5 + (size_t)oi * 5;
        const float* p3 = k3 + (size_t)oi * 3;
        const float bse = g4v * a5[oi];
        const float c3v = g3v * a3[oi];
        float wv[5];
        wv[0] = g0 * p5[0] + bse;
        wv[1] = g0 * p5[1] + bse;
        wv[2] = g0 * p5[2] + g1 * p3[0] + c3v + bse;
        wv[3] = g0 * p5[3] + g1 * p3[1] + c3v + bse;
        wv[4] = g0 * p5[4] + g1 * p3[2] + c3v + g2 * k1[oi] + bse;
        const size_t idx0 = (((size_t)n * 5 * HF + hf) * 128 + o) * 64 + ii;
#pragma unroll
        for (int k = 0; k < 5; k++)
            wh[idx0 + k * kstride] = __float2half_rn(wv[k]);
    }
}

// ---------------- downsample weight reorder (+ zero bn accums) -------
__global__ void split_dw_kernel(const float* __restrict__ dw,
                                __half* __restrict__ wdh,
                                float* __restrict__ B1, float* __restrict__ B2)
{
    int idx = blockIdx.x * 256 + threadIdx.x;
    if (blockIdx.x == 0) {
        if (threadIdx.x < CO) B1[threadIdx.x] = 0.f;
        else B2[threadIdx.x - CO] = 0.f;
    }
    if (idx >= CO * 256) return;
    int o = idx >> 8, r = idx & 255;
    int kk = r >> 7, ifull = r & 127;
    float v = dw[(size_t)o * 256 + ifull * 2 + kk];
    size_t out = (((size_t)kk * 2 + (ifull >> 6)) * 128 + o) * 64 + (ifull & 63);
    wdh[out] = __float2half_rn(v);
}

// ---------------- norm + mish + transpose v2 ----------------
// 64-wide l tile, half2 phase-1 loads, pitch-65 fp32 tile.
// grid (LL/64, NN), block 256.
__global__ void __launch_bounds__(256)
norm_transpose_kernel(const __half* __restrict__ y,
                      const float* __restrict__ S1,
                      const float* __restrict__ S2,
                      const float* __restrict__ gamma,
                      const float* __restrict__ beta,
                      float* __restrict__ out_full,
                      __half* __restrict__ out_hi)
{
    __shared__ float tile[CO][65];
    __shared__ float sc[CO], sh[CO];
    int n = blockIdx.y, l0 = blockIdx.x * 64;
    int tid = threadIdx.x;
    if (tid < CO) {
        int no = n * CO + tid;
        float mu = S1[no] * (1.f / LL);
        float var = S2[no] * (1.f / LL) - mu * mu;
        float s = gamma[tid] * rsqrtf(var + 1e-5f);
        sc[tid] = s;
        sh[tid] = beta[tid] - mu * s;
    }
    __syncthreads();
    {   // phase 1: half2 along l, 8 o-groups
        int lt = tid & 31, ob = tid >> 5;
#pragma unroll
        for (int r = 0; r < 16; r++) {
            int o = ob + 8 * r;
            __half2 hv = *(const __half2*)&y[((size_t)(n * CO + o)) * LL + l0 + 2 * lt];
            float2 f = __half22float2(hv);
            float s = sc[o], b = sh[o];
            tile[o][2 * lt]     = mishf(f.x * s + b);
            tile[o][2 * lt + 1] = mishf(f.y * s + b);
        }
    }
    __syncthreads();
    {   // phase 2: coalesced along o
        int oc = tid & 127, lb = tid >> 7;
#pragma unroll
        for (int ly = lb; ly < 64; ly += 2) {
            size_t idx = ((size_t)n * LL + l0 + ly) * CO + oc;
            float v = tile[oc][ly];
            if (out_full) out_full[idx] = v;
            out_hi[idx] = __float2half_rn(v);
        }
    }
}

// ---------------- batch-norm apply (finalize fused) ----------------
__global__ void bn_apply_kernel(const float* __restrict__ xd,
                                const float* __restrict__ B1,
                                const float* __restrict__ B2,
                                const float* __restrict__ dg,
                                const float* __restrict__ db,
                                float* __restrict__ out)
{
    size_t i4 = (size_t)blockIdx.x * 256 + threadIdx.x;
    const size_t total4 = (size_t)NN * CO * LO / 4;
    if (i4 >= total4) return;
    float4 v = ((const float4*)xd)[i4];
    int o = (int)((i4 * 4 / LO) & (CO - 1));
    const float cnt = (float)NN * LO;
    float mu = B1[o] / cnt;
    float var = B2[o] / cnt - mu * mu;
    float sc = dg[o] * rsqrtf(var + 1e-5f);
    float sh = db[o] - mu * sc;
    float4 r;
    r.x = mishf(v.x * sc + sh);
    r.y = mishf(v.y * sc + sh);
    r.z = mishf(v.z * sc + sh);
    r.w = mishf(v.w * sc + sh);
    ((float4*)out)[i4] = r;
}

// ---------------- launch ----------------
extern "C" void kernel_launch(void* const* d_in, const int* in_sizes, int n_in,
                              void* d_out, int out_size)
{
    const float* x        = (const float*)d_in[0];
    const float* t        = (const float*)d_in[1];
    const float* l1_k5    = (const float*)d_in[2];
    const float* l1_k3    = (const float*)d_in[3];
    const float* l1_k1    = (const float*)d_in[4];
    const float* l1_a3    = (const float*)d_in[5];
    const float* l1_a5    = (const float*)d_in[6];
    const float* l1_gw    = (const float*)d_in[7];
    const float* l1_gb    = (const float*)d_in[8];
    const float* l1_gamma = (const float*)d_in[9];
    const float* l1_beta  = (const float*)d_in[10];
    const float* l2_k5    = (const float*)d_in[11];
    const float* l2_k3    = (const float*)d_in[12];
    const float* l2_k1    = (const float*)d_in[13];
    const float* l2_a3    = (const float*)d_in[14];
    const float* l2_a5    = (const float*)d_in[15];
    const float* l2_gw    = (const float*)d_in[16];
    const float* l2_gb    = (const float*)d_in[17];
    const float* l2_gamma = (const float*)d_in[18];
    const float* l2_beta  = (const float*)d_in[19];
    const float* dw       = (const float*)d_in[20];
    const float* dg       = (const float*)d_in[21];
    const float* db       = (const float*)d_in[22];

    float* out      = (float*)d_out;
    float* out_xd   = out;
    float* out_skip = out + (size_t)NN * CO * LO;

    __half *hh, *ssh, *ybuf, *w1h, *w2h, *wdh;
    float *xdbuf, *s1, *s2, *b1, *b2;
    cudaGetSymbolAddress((void**)&hh, g_hh);
    cudaGetSymbolAddress((void**)&ssh, g_ssh);
    cudaGetSymbolAddress((void**)&ybuf, g_y);
    cudaGetSymbolAddress((void**)&w1h, g_w1h);
    cudaGetSymbolAddress((void**)&w2h, g_w2h);
    cudaGetSymbolAddress((void**)&wdh, g_wdh);
    cudaGetSymbolAddress((void**)&xdbuf, g_xd);
    cudaGetSymbolAddress((void**)&s1, g_s1);
    cudaGetSymbolAddress((void**)&s2, g_s2);
    cudaGetSymbolAddress((void**)&b1, g_b1);
    cudaGetSymbolAddress((void**)&b2, g_b2);

    // smem: XT + 2 W buffers
    const int SM1 = 260 * 144 + 2 * 9216;   // 55872   (NT=256)
    const int SM2 = 260 * 272 + 2 * 9216;   // 89152   (NT=256)
    const int SMD = 256 * 272 + 2 * 9216;   // 88064   (NT=128, RS=2)
    cudaFuncSetAttribute((const void*)mma_conv<64, 5, 1, 4, 256, true, __half, float>,
                         cudaFuncAttributeMaxDynamicSharedMemorySize, SM1);
    cudaFuncSetAttribute((const void*)mma_conv<128, 5, 1, 4, 256, true, __half, __half>,
                         cudaFuncAttributeMaxDynamicSharedMemorySize, SM2);
    cudaFuncSetAttribute((const void*)mma_conv<128, 2, 2, 0, 128, false, float, __half>,
                         cudaFuncAttributeMaxDynamicSharedMemorySize, SMD);

    // layer 1 (reads raw fp32 x; conversion fused into loader)
    gate_weights_kernel<<<dim3(NN, CI1 / 64, 4), 512>>>(t, l1_gw, l1_gb, l1_k5, l1_k3, l1_k1,
                                                        l1_a3, l1_a5, w1h, s1, s2, CI1);
    mma_conv<64, 5, 1, 4, 256, true, __half, float><<<dim3(LL / 256, NN, 2), 256, SM1>>>(
        x, w1h, ybuf, s1, s2, (size_t)LL * CI1, (size_t)5 * 1 * CO * 64, LL);
    norm_transpose_kernel<<<dim3(LL / 64, NN), 256>>>(ybuf, s1, s2, l1_gamma, l1_beta,
                                                      nullptr, hh);

    // layer 2
    gate_weights_kernel<<<dim3(NN, CO / 64, 4), 512>>>(t, l2_gw, l2_gb, l2_k5, l2_k3, l2_k1,
                                                       l2_a3, l2_a5, w2h, s1, s2, CO);
    mma_conv<128, 5, 1, 4, 256, true, __half, __half><<<dim3(LL / 256, NN, 2), 256, SM2>>>(
        hh, w2h, ybuf, s1, s2, (size_t)LL * CO, (size_t)5 * 2 * CO * 64, LL);
    norm_transpose_kernel<<<dim3(LL / 64, NN), 256>>>(ybuf, s1, s2, l2_gamma, l2_beta,
                                                      out_skip, ssh);

    // downsample + BN + mish
    split_dw_kernel<<<(CO * 256 + 255) / 256, 256>>>(dw, wdh, b1, b2);
    mma_conv<128, 2, 2, 0, 128, false, float, __half><<<dim3(LO / 128, NN, 2), 256, SMD>>>(
        ssh, wdh, xdbuf, b1, b2, (size_t)LL * CO, 0, LO);
    bn_apply_kernel<<<(int)(((size_t)NN * CO * LO / 4 + 255) / 256), 256>>>(
        xdbuf, b1, b2, dg, db, out_xd);
}

// round 16
// speedup vs baseline: 1.0692x; 1.0692x over previous
#include <cuda_runtime.h>
#include <cuda_fp16.h>
#include <math.h>
#include <stdint.h>

#define NN 32
#define LL 8192
#define CO 128
#define CI1 64
#define TT 10
#define LO 4096

// ---------------- scratch (__device__ globals; no allocation) ----------------
__device__ __align__(128) __half g_xh[(size_t)NN * LL * CI1];
__device__ __align__(128) __half g_hh[(size_t)NN * LL * CO];
__device__ __align__(128) __half g_ssh[(size_t)NN * LL * CO];
__device__ __align__(128) __half g_y[(size_t)NN * CO * LL];
__device__ __align__(128) float g_xd[(size_t)NN * CO * LO];
__device__ __align__(128) __half g_w1h[(size_t)NN * 5 * 1 * CO * 64];
__device__ __align__(128) __half g_w2h[(size_t)NN * 5 * 2 * CO * 64];
__device__ __align__(128) __half g_wdh[4 * CO * 64];
__device__ float g_s1[NN * CO];
__device__ float g_s2[NN * CO];
__device__ float g_b1[CO];
__device__ float g_b2[CO];

// ---------------- small device helpers ----------------
// Fast mish: x * tanh(softplus(x)) = x*((1+e)^2-1)/((1+e)^2+1), e = exp(x).
__device__ __forceinline__ float mishf(float v) {
    if (v > 8.f) return v;
    float e = __expf(v);
    float t = 1.f + e;
    float t2 = t * t;
    return v * __fdividef(t2 - 1.f, t2 + 1.f);
}
__device__ __forceinline__ uint32_t smem_u32(const void* p) {
    uint32_t a;
    asm("{ .reg .u64 t; cvta.to.shared.u64 t, %1; cvt.u32.u64 %0, t; }" : "=r"(a) : "l"(p));
    return a;
}
__device__ __forceinline__ void cp16(uint32_t dst, const void* src) {
    asm volatile("cp.async.cg.shared.global [%0], [%1], 16;" :: "r"(dst), "l"(src));
}
__device__ __forceinline__ void cp_commit() {
    asm volatile("cp.async.commit_group;" ::: "memory");
}
template <int N>
__device__ __forceinline__ void cp_wait() {
    asm volatile("cp.async.wait_group %0;" :: "n"(N) : "memory");
}
__device__ __forceinline__ void ldsm4(uint32_t* r, uint32_t addr) {
    asm volatile("ldmatrix.sync.aligned.m8n8.x4.shared.b16 {%0,%1,%2,%3}, [%4];"
                 : "=r"(r[0]), "=r"(r[1]), "=r"(r[2]), "=r"(r[3]) : "r"(addr));
}
__device__ __forceinline__ void mma_f16(float* d, const uint32_t* a, const uint32_t* b) {
    asm volatile("mma.sync.aligned.m16n8k16.row.col.f32.f16.f16.f32 "
                 "{%0,%1,%2,%3}, {%4,%5,%6,%7}, {%8,%9}, {%0,%1,%2,%3};"
                 : "+f"(d[0]), "+f"(d[1]), "+f"(d[2]), "+f"(d[3])
                 : "r"(a[0]), "r"(a[1]), "r"(a[2]), "r"(a[3]), "r"(b[0]), "r"(b[1]));
}

// ============================================================================
// Conv-as-GEMM, warp-level fp16 MMA (single fp16 W).
// X: fp16 source, cp.async fill committed as its own group.
// YT = __half (layers 1/2) or float (downsample). Fused stats.
// CTA = 256 threads (8 warps, 2x4); tile M=64 (o-half, blockIdx.z) x NT.
// ============================================================================
template <int CI, int NSHIFT, int RS, int HALO, int NT, bool PER_N_STATS, typename YT>
__global__ void __launch_bounds__(256, 2)
mma_conv(const __half* __restrict__ X,
         const __half* __restrict__ Wh,
         YT* __restrict__ Y, float* __restrict__ S1, float* __restrict__ S2,
         size_t x_nstride, size_t w_nstride, int outL)
{
    constexpr int HF = CI / 64;
    constexpr int P = NSHIFT * HF;
    constexpr int XR = NT * RS + HALO;
    constexpr int XPITCH = CI * 2 + 16;      // bytes; row step ≡ 4 banks (mod 32)
    constexpr int WPITCH = 144;
    constexpr int WCH = 64 * WPITCH;
    constexpr int XT_B = XR * XPITCH;
    constexpr int SEGR = CI / 8;
    constexpr int NB = NT / 64;
    constexpr int NFR = 2 * NB;

    extern __shared__ char sm[];
    const uint32_t base = smem_u32(sm);
    const uint32_t x_s = base;
    const uint32_t w_s = base + XT_B;

    const int tid = threadIdx.x;
    const int n = blockIdx.y;
    const int l0 = blockIdx.x * NT;
    const int o_base = blockIdx.z * 64;

    // W piece 0 (committed group; overlaps the X fill below)
    auto load_w = [&](int piece, int buf) {
        const __half* ph = Wh + (size_t)n * w_nstride + (size_t)piece * (CO * 64)
                           + (size_t)o_base * 64;
        uint32_t dst = w_s + (uint32_t)buf * WCH;
        for (int s = tid; s < 512; s += 256) {
            int r = s >> 3, c = s & 7;
            cp16(dst + r * WPITCH + c * 16, ph + r * 64 + c * 8);
        }
        cp_commit();
    };
    load_w(0, 0);

    // ---------------- X tile fill (cp.async, own committed group) ----------------
    {
        if (HALO > 0 && blockIdx.x == 0) {
            const uint4 z = make_uint4(0, 0, 0, 0);
            for (int s = tid; s < HALO * SEGR; s += 256) {
                int r = s / SEGR, c = s % SEGR;
                *(uint4*)(sm + r * XPITCH + c * 16) = z;
            }
        }
        const __half* gx = X + (size_t)n * x_nstride;
        for (int s = tid; s < XR * SEGR; s += 256) {
            int r = s / SEGR, c = s % SEGR;
            long l = (long)l0 * RS - HALO + r;
            if (l >= 0)
                cp16(x_s + r * XPITCH + c * 16, gx + (size_t)l * CI + (size_t)c * 8);
        }
        cp_commit();
    }

    const int warp = tid >> 5, lane = tid & 31;
    const int o0w = (warp >> 2) * 32;
    const int n0w = (warp & 3) * (NT / 4);
    const int a_row = (lane & 7) + ((lane >> 3) & 1) * 8;
    const int a_csh = (lane >> 4) * 8;
    const int b_jj = (lane & 7) + ((lane >> 4) << 3);
    const int b_csh = ((lane >> 3) & 1) * 8;

    float acc[2][NFR][4];
#pragma unroll
    for (int mi = 0; mi < 2; mi++)
#pragma unroll
        for (int nf = 0; nf < NFR; nf++)
#pragma unroll
            for (int q = 0; q < 4; q++) acc[mi][nf][q] = 0.f;

    for (int p = 0; p < P; p++) {
        cp_wait<0>();
        __syncthreads();   // readers of buffer (p+1)&1 (= piece p-1) are done
        if (p + 1 < P) load_w(p + 1, (p + 1) & 1);

        const int k = p / HF, hf = p % HF;
        const uint32_t wh_b = w_s + (uint32_t)(p & 1) * WCH;

#pragma unroll
        for (int i16 = 0; i16 < 4; i16++) {
            const int i0 = i16 * 16;
            uint32_t Ah[2][4];
#pragma unroll
            for (int mi = 0; mi < 2; mi++) {
                uint32_t ao = (uint32_t)((o0w + a_row + mi * 16) * WPITCH + (i0 + a_csh) * 2);
                ldsm4(Ah[mi], wh_b + ao);
            }
            const int xcol = (hf * 64 + i0 + b_csh) * 2;
#pragma unroll
            for (int nb = 0; nb < NB; nb++) {
                uint32_t B[4];
                uint32_t xo = (uint32_t)((RS * (n0w + nb * 16 + b_jj) + k) * XPITCH + xcol);
                ldsm4(B, x_s + xo);
#pragma unroll
                for (int mi = 0; mi < 2; mi++)
#pragma unroll
                    for (int hl = 0; hl < 2; hl++)
                        mma_f16(acc[mi][nb * 2 + hl], Ah[mi], &B[hl * 2]);
            }
        }
    }

    // ---------------- epilogue: store + fused stats ----------------
    const int g = lane >> 2, tg = lane & 3;
#pragma unroll
    for (int mi = 0; mi < 2; mi++) {
        const int o = o_base + o0w + mi * 16 + g;
        YT* row0 = Y + ((size_t)(n * CO + o)) * outL + l0 + n0w;
        YT* row1 = row0 + (size_t)8 * outL;
#pragma unroll
        for (int nf = 0; nf < NFR; nf++) {
            int c = nf * 8 + tg * 2;
            if (sizeof(YT) == 2) {
                *(__half2*)((__half*)row0 + c) = __floats2half2_rn(acc[mi][nf][0], acc[mi][nf][1]);
                *(__half2*)((__half*)row1 + c) = __floats2half2_rn(acc[mi][nf][2], acc[mi][nf][3]);
            } else {
                *(float2*)((float*)row0 + c) = make_float2(acc[mi][nf][0], acc[mi][nf][1]);
                *(float2*)((float*)row1 + c) = make_float2(acc[mi][nf][2], acc[mi][nf][3]);
            }
        }
    }
    float ts[4], tq[4];
#pragma unroll
    for (int r = 0; r < 4; r++) { ts[r] = 0.f; tq[r] = 0.f; }
#pragma unroll
    for (int mi = 0; mi < 2; mi++)
#pragma unroll
        for (int nf = 0; nf < NFR; nf++) {
            float a0 = acc[mi][nf][0], a1 = acc[mi][nf][1];
            float a2 = acc[mi][nf][2], a3 = acc[mi][nf][3];
            ts[2 * mi]     += a0 + a1;  tq[2 * mi]     += a0 * a0 + a1 * a1;
            ts[2 * mi + 1] += a2 + a3;  tq[2 * mi + 1] += a2 * a2 + a3 * a3;
        }
#pragma unroll
    for (int r = 0; r < 4; r++) {
        ts[r] += __shfl_xor_sync(0xffffffffu, ts[r], 1);
        ts[r] += __shfl_xor_sync(0xffffffffu, ts[r], 2);
        tq[r] += __shfl_xor_sync(0xffffffffu, tq[r], 1);
        tq[r] += __shfl_xor_sync(0xffffffffu, tq[r], 2);
    }
    if (tg == 0) {
        const int sbase = PER_N_STATS ? n * CO : 0;
#pragma unroll
        for (int r = 0; r < 4; r++) {
            int o = o_base + o0w + (r >> 1) * 16 + g + (r & 1) * 8;
            atomicAdd(&S1[sbase + o], ts[r]);
            atomicAdd(&S2[sbase + o], tq[r]);
        }
    }
}

// ---------------- fp32 -> fp16 ----------------
__global__ void split_x_kernel(const float* __restrict__ src,
                               __half* __restrict__ hi, size_t count4)
{
    size_t i = (size_t)blockIdx.x * 256 + threadIdx.x;
    if (i >= count4) return;
    float4 v = ((const float4*)src)[i];
    ((__half2*)hi)[2 * i]     = __floats2half2_rn(v.x, v.y);
    ((__half2*)hi)[2 * i + 1] = __floats2half2_rn(v.z, v.w);
}

// ---------------- gate + per-sample weights (fp16) ----------------
__global__ void __launch_bounds__(512)
gate_weights_kernel(const float* __restrict__ t,
                    const float* __restrict__ gw,
                    const float* __restrict__ gb,
                    const float* __restrict__ k5,
                    const float* __restrict__ k3,
                    const float* __restrict__ k1,
                    const float* __restrict__ a3,
                    const float* __restrict__ a5,
                    __half* __restrict__ wh,
                    float* __restrict__ S1, float* __restrict__ S2,
                    int CI)
{
    const int n = blockIdx.x;
    const int hf = blockIdx.y;
    const int HF = gridDim.y;
    const int oc = blockIdx.z;
    const int tid = threadIdx.x;

    __shared__ float gs[5][128];
    if (tid < 128) {
        const int o = tid;
        if (blockIdx.y == 0 && blockIdx.z == 0) {
            S1[n * CO + o] = 0.f;
            S2[n * CO + o] = 0.f;
        }
        float tv[TT];
#pragma unroll
        for (int j = 0; j < TT; j++) tv[j] = t[n * TT + j];
        float g[5];
        float mx = -1e30f;
#pragma unroll
        for (int e = 0; e < 5; e++) {
            float s = gb[e * CO + o];
            const float* gwr = gw + (size_t)(e * CO + o) * TT;
#pragma unroll
            for (int j = 0; j < TT; j++) s += tv[j] * gwr[j];
            g[e] = s;
            mx = fmaxf(mx, s);
        }
        float den = 0.f;
#pragma unroll
        for (int e = 0; e < 5; e++) { g[e] = expf(g[e] - mx); den += g[e]; }
        float inv = 1.f / den;
        gs[0][o] = g[0] * inv;
        gs[1][o] = g[1] * inv;
        gs[2][o] = g[2] * inv;
        gs[3][o] = g[3] * inv * (1.f / 3.f);
        gs[4][o] = g[4] * inv * 0.2f;
    }
    __syncthreads();

    const int og = tid >> 6;
    const int ii = tid & 63;
    const int i = hf * 64 + ii;
    const size_t kstride = (size_t)HF * 128 * 64;

#pragma unroll
    for (int oj = 0; oj < 4; oj++) {
        const int o = oc * 32 + oj * 8 + og;
        const float g0 = gs[0][o], g1 = gs[1][o], g2 = gs[2][o];
        const float g3v = gs[3][o], g4v = gs[4][o];
        const int oi = o * CI + i;
        const float* p5 = k5 + (size_t)oi * 5;
        const float* p3 = k3 + (size_t)oi * 3;
        const float bse = g4v * a5[oi];
        const float c3v = g3v * a3[oi];
        float wv[5];
        wv[0] = g0 * p5[0] + bse;
        wv[1] = g0 * p5[1] + bse;
        wv[2] = g0 * p5[2] + g1 * p3[0] + c3v + bse;
        wv[3] = g0 * p5[3] + g1 * p3[1] + c3v + bse;
        wv[4] = g0 * p5[4] + g1 * p3[2] + c3v + g2 * k1[oi] + bse;
        const size_t idx0 = (((size_t)n * 5 * HF + hf) * 128 + o) * 64 + ii;
#pragma unroll
        for (int k = 0; k < 5; k++)
            wh[idx0 + k * kstride] = __float2half_rn(wv[k]);
    }
}

// ---------------- downsample weight reorder (+ zero bn accums) -------
__global__ void split_dw_kernel(const float* __restrict__ dw,
                                __half* __restrict__ wdh,
                                float* __restrict__ B1, float* __restrict__ B2)
{
    int idx = blockIdx.x * 256 + threadIdx.x;
    if (blockIdx.x == 0) {
        if (threadIdx.x < CO) B1[threadIdx.x] = 0.f;
        else B2[threadIdx.x - CO] = 0.f;
    }
    if (idx >= CO * 256) return;
    int o = idx >> 8, r = idx & 255;
    int kk = r >> 7, ifull = r & 127;
    float v = dw[(size_t)o * 256 + ifull * 2 + kk];
    size_t out = (((size_t)kk * 2 + (ifull >> 6)) * 128 + o) * 64 + (ifull & 63);
    wdh[out] = __float2half_rn(v);
}

// ---------------- norm + mish + transpose v2 ----------------
// 64-wide l tile, half2 phase-1 loads, pitch-65 fp32 tile.
// grid (LL/64, NN), block 256.
__global__ void __launch_bounds__(256)
norm_transpose_kernel(const __half* __restrict__ y,
                      const float* __restrict__ S1,
                      const float* __restrict__ S2,
                      const float* __restrict__ gamma,
                      const float* __restrict__ beta,
                      float* __restrict__ out_full,
                      __half* __restrict__ out_hi)
{
    __shared__ float tile[CO][65];
    __shared__ float sc[CO], sh[CO];
    int n = blockIdx.y, l0 = blockIdx.x * 64;
    int tid = threadIdx.x;
    if (tid < CO) {
        int no = n * CO + tid;
        float mu = S1[no] * (1.f / LL);
        float var = S2[no] * (1.f / LL) - mu * mu;
        float s = gamma[tid] * rsqrtf(var + 1e-5f);
        sc[tid] = s;
        sh[tid] = beta[tid] - mu * s;
    }
    __syncthreads();
    {   // phase 1: half2 along l, 8 o-groups
        int lt = tid & 31, ob = tid >> 5;
#pragma unroll
        for (int r = 0; r < 16; r++) {
            int o = ob + 8 * r;
            __half2 hv = *(const __half2*)&y[((size_t)(n * CO + o)) * LL + l0 + 2 * lt];
            float2 f = __half22float2(hv);
            float s = sc[o], b = sh[o];
            tile[o][2 * lt]     = mishf(f.x * s + b);
            tile[o][2 * lt + 1] = mishf(f.y * s + b);
        }
    }
    __syncthreads();
    {   // phase 2: coalesced along o
        int oc = tid & 127, lb = tid >> 7;
#pragma unroll
        for (int ly = lb; ly < 64; ly += 2) {
            size_t idx = ((size_t)n * LL + l0 + ly) * CO + oc;
            float v = tile[oc][ly];
            if (out_full) out_full[idx] = v;
            out_hi[idx] = __float2half_rn(v);
        }
    }
}

// ---------------- batch-norm apply (finalize fused) ----------------
__global__ void bn_apply_kernel(const float* __restrict__ xd,
                                const float* __restrict__ B1,
                                const float* __restrict__ B2,
                                const float* __restrict__ dg,
                                const float* __restrict__ db,
                                float* __restrict__ out)
{
    size_t i4 = (size_t)blockIdx.x * 256 + threadIdx.x;
    const size_t total4 = (size_t)NN * CO * LO / 4;
    if (i4 >= total4) return;
    float4 v = ((const float4*)xd)[i4];
    int o = (int)((i4 * 4 / LO) & (CO - 1));
    const float cnt = (float)NN * LO;
    float mu = B1[o] / cnt;
    float var = B2[o] / cnt - mu * mu;
    float sc = dg[o] * rsqrtf(var + 1e-5f);
    float sh = db[o] - mu * sc;
    float4 r;
    r.x = mishf(v.x * sc + sh);
    r.y = mishf(v.y * sc + sh);
    r.z = mishf(v.z * sc + sh);
    r.w = mishf(v.w * sc + sh);
    ((float4*)out)[i4] = r;
}

// ---------------- launch ----------------
extern "C" void kernel_launch(void* const* d_in, const int* in_sizes, int n_in,
                              void* d_out, int out_size)
{
    const float* x        = (const float*)d_in[0];
    const float* t        = (const float*)d_in[1];
    const float* l1_k5    = (const float*)d_in[2];
    const float* l1_k3    = (const float*)d_in[3];
    const float* l1_k1    = (const float*)d_in[4];
    const float* l1_a3    = (const float*)d_in[5];
    const float* l1_a5    = (const float*)d_in[6];
    const float* l1_gw    = (const float*)d_in[7];
    const float* l1_gb    = (const float*)d_in[8];
    const float* l1_gamma = (const float*)d_in[9];
    const float* l1_beta  = (const float*)d_in[10];
    const float* l2_k5    = (const float*)d_in[11];
    const float* l2_k3    = (const float*)d_in[12];
    const float* l2_k1    = (const float*)d_in[13];
    const float* l2_a3    = (const float*)d_in[14];
    const float* l2_a5    = (const float*)d_in[15];
    const float* l2_gw    = (const float*)d_in[16];
    const float* l2_gb    = (const float*)d_in[17];
    const float* l2_gamma = (const float*)d_in[18];
    const float* l2_beta  = (const float*)d_in[19];
    const float* dw       = (const float*)d_in[20];
    const float* dg       = (const float*)d_in[21];
    const float* db       = (const float*)d_in[22];

    float* out      = (float*)d_out;
    float* out_xd   = out;
    float* out_skip = out + (size_t)NN * CO * LO;

    __half *xh, *hh, *ssh, *ybuf, *w1h, *w2h, *wdh;
    float *xdbuf, *s1, *s2, *b1, *b2;
    cudaGetSymbolAddress((void**)&xh, g_xh);
    cudaGetSymbolAddress((void**)&hh, g_hh);
    cudaGetSymbolAddress((void**)&ssh, g_ssh);
    cudaGetSymbolAddress((void**)&ybuf, g_y);
    cudaGetSymbolAddress((void**)&w1h, g_w1h);
    cudaGetSymbolAddress((void**)&w2h, g_w2h);
    cudaGetSymbolAddress((void**)&wdh, g_wdh);
    cudaGetSymbolAddress((void**)&xdbuf, g_xd);
    cudaGetSymbolAddress((void**)&s1, g_s1);
    cudaGetSymbolAddress((void**)&s2, g_s2);
    cudaGetSymbolAddress((void**)&b1, g_b1);
    cudaGetSymbolAddress((void**)&b2, g_b2);

    // smem: XT + 2 W buffers
    const int SM1 = 260 * 144 + 2 * 9216;   // 55872   (NT=256)
    const int SM2 = 260 * 272 + 2 * 9216;   // 89152   (NT=256)
    const int SMD = 256 * 272 + 2 * 9216;   // 88064   (NT=128, RS=2)
    cudaFuncSetAttribute((const void*)mma_conv<64, 5, 1, 4, 256, true, __half>,
                         cudaFuncAttributeMaxDynamicSharedMemorySize, SM1);
    cudaFuncSetAttribute((const void*)mma_conv<128, 5, 1, 4, 256, true, __half>,
                         cudaFuncAttributeMaxDynamicSharedMemorySize, SM2);
    cudaFuncSetAttribute((const void*)mma_conv<128, 2, 2, 0, 128, false, float>,
                         cudaFuncAttributeMaxDynamicSharedMemorySize, SMD);

    // x -> fp16
    {
        size_t c4 = (size_t)NN * LL * CI1 / 4;
        split_x_kernel<<<(int)((c4 + 255) / 256), 256>>>(x, xh, c4);
    }

    // layer 1
    gate_weights_kernel<<<dim3(NN, CI1 / 64, 4), 512>>>(t, l1_gw, l1_gb, l1_k5, l1_k3, l1_k1,
                                                        l1_a3, l1_a5, w1h, s1, s2, CI1);
    mma_conv<64, 5, 1, 4, 256, true, __half><<<dim3(LL / 256, NN, 2), 256, SM1>>>(
        xh, w1h, ybuf, s1, s2, (size_t)LL * CI1, (size_t)5 * 1 * CO * 64, LL);
    norm_transpose_kernel<<<dim3(LL / 64, NN), 256>>>(ybuf, s1, s2, l1_gamma, l1_beta,
                                                      nullptr, hh);

    // layer 2
    gate_weights_kernel<<<dim3(NN, CO / 64, 4), 512>>>(t, l2_gw, l2_gb, l2_k5, l2_k3, l2_k1,
                                                       l2_a3, l2_a5, w2h, s1, s2, CO);
    mma_conv<128, 5, 1, 4, 256, true, __half><<<dim3(LL / 256, NN, 2), 256, SM2>>>(
        hh, w2h, ybuf, s1, s2, (size_t)LL * CO, (size_t)5 * 2 * CO * 64, LL);
    norm_transpose_kernel<<<dim3(LL / 64, NN), 256>>>(ybuf, s1, s2, l2_gamma, l2_beta,
                                                      out_skip, ssh);

    // downsample + BN + mish
    split_dw_kernel<<<(CO * 256 + 255) / 256, 256>>>(dw, wdh, b1, b2);
    mma_conv<128, 2, 2, 0, 128, false, float><<<dim3(LO / 128, NN, 2), 256, SMD>>>(
        ssh, wdh, xdbuf, b1, b2, (size_t)LL * CO, 0, LO);
    bn_apply_kernel<<<(int)(((size_t)NN * CO * LO / 4 + 255) / 256), 256>>>(
        xdbuf, b1, b2, dg, db, out_xd);
}